// round 13
// baseline (speedup 1.0000x reference)
#include <cuda_runtime.h>
#include <math.h>

#define B_  8
#define T_  4096
#define D_  1024
#define D4_ 256
#define S_  16
#define H_  256
#define W_  241
#define NP_ 256
#define RB_ 8

typedef unsigned long long u64;

// Packed f32x2 helpers (sm_103a; PTX-only encodings)
#define ADDX2(out, a, b) \
  asm("add.rn.f32x2 %0, %1, %2;" : "=l"(out) : "l"(a), "l"(b))
#define FMAX2(out, a, b, c) \
  asm("fma.rn.f32x2 %0, %1, %2, %3;" : "=l"(out) : "l"(a), "l"(b), "l"(c))
__device__ __forceinline__ u64 packf2(float lo, float hi) {
  u64 v;
  asm("mov.b64 %0, {%1, %2};" : "=l"(v) : "f"(lo), "f"(hi));
  return v;
}

// cp.async (LDGSTS): fire-and-forget 16B global->shared, no register dep.
__device__ __forceinline__ void cpa16(unsigned int dst, const float4* src) {
  asm volatile("cp.async.cg.shared.global [%0], [%1], 16;"
               :: "r"(dst), "l"(src));
}
#define CPA_COMMIT() asm volatile("cp.async.commit_group;" ::: "memory")
#define CPA_WAIT(n)  asm volatile("cp.async.wait_group %0;" :: "n"(n) : "memory")

// Cross-CTA scratch: per-(pair,rowblock) column partial sums + shift partials.
__device__ float g_partial[NP_][RB_][D_];
__device__ float g_shiftp[NP_][RB_];
__device__ unsigned int g_count[NP_];   // zero-init; finalizer resets -> replay-safe

__constant__ int c_alias[64] = {
  -1,-1,-1,-1,-1,-1,-1,-1,-1,-1,   // 0-9
  -1,11,-1,11,-1,-1,11,-1,-1,-1,   // 10-19
  -1,21,21,21,-1,-1,-1,-1,-1,-1,   // 20-29
  -1,31,31,31,-1,-1,-1,-1,-1,-1,   // 30-39
  -1,41,41,41,41,-1,-1,-1,-1,-1,   // 40-49
  -1,51,51,51,-1,-1,-1,-1,-1,-1,   // 50-59
  -1,-1,-1,-1                      // 60-63
};

__device__ __forceinline__ float bsum(float v, volatile float* sred) {
#pragma unroll
  for (int o = 16; o; o >>= 1) v += __shfl_xor_sync(0xffffffffu, v, o);
  __syncthreads();
  if ((threadIdx.x & 31) == 0) sred[threadIdx.x >> 5] = v;
  __syncthreads();
  float t = 0.f;
#pragma unroll
  for (int i = 0; i < 8; i++) t += sred[i];
  return t;
}
__device__ __forceinline__ float bmax(float v, volatile float* sred) {
#pragma unroll
  for (int o = 16; o; o >>= 1) v = fmaxf(v, __shfl_xor_sync(0xffffffffu, v, o));
  __syncthreads();
  if ((threadIdx.x & 31) == 0) sred[threadIdx.x >> 5] = v;
  __syncthreads();
  float t = sred[0];
#pragma unroll
  for (int i = 1; i < 8; i++) t = fmaxf(t, sred[i]);
  return t;
}

// ---------------------------------------------------------------------------
// Single kernel, grid (8 rowblocks FAST, 256 pairs SLOW).
// Streaming phase: 2-stage cp.async smem pipeline (stage = 4 rows = 16 KB).
// cp.async has no destination register -> in-flight bytes are no longer
// limited by the register file (the measured ~3.5 TB/s wall of rounds 6-12).
// Compute: LDS.128 from the ready stage + packed f32x2 math.
// The 8th CTA to finish a pair runs the finalize inline (fence+atomic).
// ---------------------------------------------------------------------------
__global__ void __launch_bounds__(256, 4) k_all(
    const float* __restrict__ hidden, const float* __restrict__ anchor,
    const int* __restrict__ ids, const int* __restrict__ anchor_end,
    float* __restrict__ out) {
  __shared__ float4 s_stage[2][1024];    // 32 KB (reused as swarp after stream)
  __shared__ ulonglong2 snega[D4_];      // 4 KB  (negated anchor, packed)
  __shared__ float sSsq[8][8][33];       // 8.25 KB [warp][stage][lane]
  __shared__ float sred[8];
  __shared__ int ftok[H_];
  __shared__ int sspan[S_];
  __shared__ int salias[64];
  __shared__ int scnt[S_];
  __shared__ int s_last;
  __shared__ int s_root, s_hasT;
  __shared__ float s_invden;
  __shared__ unsigned long long s_dmask, s_cmask;

  const int rb = blockIdx.x, p = blockIdx.y;   // rb FAST-varying in launch order
  const int tid = threadIdx.x;
  const int warp = tid >> 5, lane = tid & 31;
  const int half = warp & 1;             // column half (0: cols 0-511, 1: 512-1023)
  const int wp = warp >> 1;              // stage-local row 0..3
  const int b = p >> 5;
  const int ae = anchor_end[p];
  const int start = ae + 1;

  const float4* anchor4 = (const float4*)(anchor + (size_t)p * D_);
  for (int i = tid; i < D4_; i += 256) {
    float4 a = __ldg(anchor4 + i);
    ulonglong2 n;
    n.x = packf2(-a.x, -a.y);
    n.y = packf2(-a.z, -a.w);
    snega[i] = n;
  }

  const float4* gbase =
      (const float4*)(hidden + ((size_t)b * T_ + start + rb * 32) * D_);
  unsigned int stg0 = (unsigned int)__cvta_generic_to_shared(&s_stage[0][0]);
  unsigned int stg1 = (unsigned int)__cvta_generic_to_shared(&s_stage[1][0]);

  // Prologue: issue stages 0 and 1 (each: 1024 x 16B, 4 per thread, coalesced)
#pragma unroll
  for (int i = 0; i < 4; i++) {
    int idx = tid + 256 * i;
    cpa16(stg0 + idx * 16, gbase + idx);
  }
  CPA_COMMIT();
#pragma unroll
  for (int i = 0; i < 4; i++) {
    int idx = tid + 256 * i;
    cpa16(stg1 + idx * 16, gbase + 1024 + idx);
  }
  CPA_COMMIT();
  __syncthreads();   // snega visible to all

  u64 c0 = 0, c1 = 0, c2 = 0, c3 = 0, c4 = 0, c5 = 0, c6 = 0, c7 = 0;

#pragma unroll
  for (int s = 0; s < 8; s++) {
    if (s < 7) { CPA_WAIT(1); } else { CPA_WAIT(0); }
    __syncthreads();   // stage s data visible to every thread

    // Warp consumes its half of stage-local row wp (global CTA row 4s+wp)
    const ulonglong2* row =
        (const ulonglong2*)&s_stage[s & 1][0] + wp * 256 + half * 128;
    u64 q0 = 0, q1 = 0;
#pragma unroll
    for (int j = 0; j < 4; j++) {
      ulonglong2 x = row[lane + 32 * j];                 // LDS.128
      ulonglong2 an = snega[half * 128 + lane + 32 * j];
      u64 d0, d1;
      switch (j) {   // packed column accumulate (compile-time reg names)
        case 0: ADDX2(c0, c0, x.x); ADDX2(c1, c1, x.y); break;
        case 1: ADDX2(c2, c2, x.x); ADDX2(c3, c3, x.y); break;
        case 2: ADDX2(c4, c4, x.x); ADDX2(c5, c5, x.y); break;
        case 3: ADDX2(c6, c6, x.x); ADDX2(c7, c7, x.y); break;
      }
      ADDX2(d0, x.x, an.x); ADDX2(d1, x.y, an.y);
      FMAX2(q0, d0, d0, q0); FMAX2(q1, d1, d1, q1);
    }
    {
      float2 a2, b2;
      asm("mov.b64 {%0, %1}, %2;" : "=f"(a2.x), "=f"(a2.y) : "l"(q0));
      asm("mov.b64 {%0, %1}, %2;" : "=f"(b2.x), "=f"(b2.y) : "l"(q1));
      sSsq[warp][s][lane] = (a2.x + a2.y) + (b2.x + b2.y);
    }
    __syncthreads();   // all warps done with buffer (s&1) before refill

    if (s < 6) {       // issue stage s+2 into the buffer just drained
      const float4* src = gbase + (size_t)(s + 2) * 1024;
      unsigned int dst = (s & 1) ? stg1 : stg0;
#pragma unroll
      for (int i = 0; i < 4; i++) {
        int idx = tid + 256 * i;
        cpa16(dst + idx * 16, src + idx);
      }
      CPA_COMMIT();
    }
  }

  // Reuse stage buffer 0 as the cross-warp column scratch (16 KB needed)
  ulonglong2* swarp = (ulonglong2*)&s_stage[0][0];
  {
    ulonglong2 v;
    v.x = c0; v.y = c1; swarp[warp * 128 + lane] = v;
    v.x = c2; v.y = c3; swarp[warp * 128 + lane + 32] = v;
    v.x = c4; v.y = c5; swarp[warp * 128 + lane + 64] = v;
    v.x = c6; v.y = c7; swarp[warp * 128 + lane + 96] = v;
  }
  __syncthreads();

  // Row shift: thread t (<32) owns row 4*(t>>2)+(t&3); sums both halves.
  if (tid < 32) {
    const int r = tid >> 2, w0 = (tid & 3) * 2;
    float s = 0.f;
#pragma unroll 8
    for (int l = 0; l < 32; l++) s += sSsq[w0][r][l] + sSsq[w0 + 1][r][l];
    float v = sqrtf(s);
#pragma unroll
    for (int o = 16; o; o >>= 1) v += __shfl_xor_sync(0xffffffffu, v, o);
    if (lane == 0) g_shiftp[p][rb] = v;
  }

  // Column combine: thread tid owns packed column tid (4 same-half warps)
  {
    const int hh = tid >> 7, cc = tid & 127;
    ulonglong2 s = swarp[hh * 128 + cc];
#pragma unroll
    for (int w = 1; w < 4; w++) {
      ulonglong2 t = swarp[(2 * w + hh) * 128 + cc];
      ADDX2(s.x, s.x, t.x);
      ADDX2(s.y, s.y, t.y);
    }
    ((ulonglong2*)g_partial[p][rb])[tid] = s;   // bit-identical to float4 layout
  }

  // ---- Arrival protocol: last CTA of the pair finalizes ----
  __threadfence();
  __syncthreads();
  if (tid == 0) {
    unsigned int old = atomicAdd(&g_count[p], 1u);
    s_last = (old == RB_ - 1) ? 1 : 0;
    if (s_last) g_count[p] = 0;   // reset for next graph replay
  }
  __syncthreads();
  if (!s_last) return;
  __threadfence();   // acquire side: order partial reads after the atomic

  // ================== FINALIZE (one CTA per pair) ==================
  ftok[tid] = ids[b * T_ + start + tid];
  if (tid < S_) sspan[tid] = ids[b * T_ + ae - (S_ - 1) + tid];
  if (tid < 64) salias[tid] = c_alias[tid];
  __syncthreads();

  // cosine sim from the 8 rowblock partials (L2-hot); anchor re-read (L2-hot)
  float dot, nm, na;
  {
    float4 s = make_float4(0.f, 0.f, 0.f, 0.f);
#pragma unroll
    for (int r = 0; r < RB_; r++) {
      float4 t = ((const float4*)g_partial[p][r])[tid];
      s.x += t.x; s.y += t.y; s.z += t.z; s.w += t.w;
    }
    const float invH = 1.f / H_;
    float4 m = make_float4(s.x * invH, s.y * invH, s.z * invH, s.w * invH);
    float4 a = __ldg(anchor4 + tid);
    dot = m.x * a.x + m.y * a.y + m.z * a.z + m.w * a.w;
    nm  = m.x * m.x + m.y * m.y + m.z * m.z + m.w * m.w;
    na  = a.x * a.x + a.y * a.y + a.z * a.z + a.w * a.w;
  }
  dot = bsum(dot, sred);
  nm = bsum(nm, sred);
  na = bsum(na, sred);
  const float eps = 1e-8f;
  float sim = dot / (fmaxf(sqrtf(na), eps) * fmaxf(sqrtf(nm), eps));
  float hidden_c = fmaxf(0.f, (1.f - sim) * 0.5f);

  int atok = sspan[S_ - 1];
  float tcnt = (ftok[tid] == atok) ? 1.f : 0.f;
  tcnt = bsum(tcnt, sred);
  float token_c = 1.f - tcnt * (1.f / H_);

  // span analysis: counts by 16 threads (no per-thread arrays -> low regs)
  if (tid < S_) {
    int tokv = sspan[tid];
    int c = 0;
    for (int s2 = 0; s2 < S_; s2++) c += (tokv == sspan[s2]);
    scnt[tid] = c;
  }
  __syncthreads();
  if (tid == 0) {
    unsigned long long dm = 0ull;
    for (int s = 0; s < S_; s++) dm |= 1ull << sspan[s];
    int denom = __popcll(dm);
    int maxc = 0;
    for (int s = 0; s < S_; s++) maxc = max(maxc, scnt[s]);
    int mode = 64;
    for (int s = 0; s < S_; s++)
      if (scnt[s] == maxc) mode = min(mode, sspan[s]);
    int root = -1;
    for (int s = 0; s < S_; s++) {
      int al = salias[sspan[s]];
      if (al >= 0) { root = al; break; }
    }
    if (root < 0) root = mode;
    unsigned long long cm = 0ull;
    switch (root) {
      case 11: cm = (1ull<<11)|(1ull<<13)|(1ull<<16); break;
      case 21: cm = (1ull<<14)|(1ull<<15)|(1ull<<21)|(1ull<<22)|(1ull<<23); break;
      case 31: cm = (1ull<<15)|(1ull<<31)|(1ull<<32)|(1ull<<33); break;
      case 41: cm = (1ull<<41)|(1ull<<42)|(1ull<<43)|(1ull<<44); break;
      case 51: cm = (1ull<<15)|(1ull<<51)|(1ull<<52)|(1ull<<53); break;
      default: break;
    }
    s_root = root;
    s_cmask = cm;
    s_hasT = (cm != 0ull) ? 1 : 0;
    s_dmask = dm;
    s_invden = 1.f / (float)denom;
  }
  __syncthreads();

  const int root = s_root;
  const unsigned long long cmask = s_cmask, dmask = s_dmask;
  const int hasT = s_hasT;
  const float invden = s_invden;

  float sims = 0.f, rp = 0.f, regime = 0.f, hit = 0.f;
  float simmax = -1e30f;
  if (tid < W_) {
    float ex = 0.f, pos = 0.f, ac = 0.f, hd = 0.f;
    unsigned long long wm = 0ull;
#pragma unroll
    for (int s = 0; s < S_; s++) {
      int tok = ftok[tid + s];
      wm |= 1ull << tok;
      float eq = (tok == sspan[s]) ? 1.f : 0.f;
      ex += eq;
      pos += eq * (1.0f - 0.04f * (float)s);
      rp += (tok == root) ? 1.f : 0.f;
      ac += (salias[tok] == root) ? 1.f : 0.f;
      hd += (float)((cmask >> tok) & 1ull);
    }
    ex *= (1.f / S_);
    pos *= (1.f / 11.2f);
    rp *= (1.f / S_);
    ac *= (1.f / S_);
    hd *= (1.f / S_);
    float ov = (float)__popcll(wm & dmask) * invden;
    regime = hasT ? (0.55f * hd + 0.2f * ov + 0.15f * ac + 0.1f * rp)
                  : (0.45f * ex + 0.3f * ov + 0.1f * ac + 0.15f * rp);
    sims = 0.25f * ex + 0.15f * ov + 0.35f * pos + 0.25f * regime;
    simmax = sims;
    hit = (sims >= 0.6f) ? 1.f : 0.f;
  }
  float sum_sims = bsum(sims, sred);
  float sum_rp   = bsum(rp, sred);
  float sum_reg  = bsum(regime, sred);
  float sum_hit  = bsum(hit, sred);
  float best     = bmax(simmax, sred);

  if (tid == 0) {
    const float invW = 1.f / (float)W_;
    float msims = sum_sims * invW;
    float mrp = sum_rp * invW;
    float mrc = sum_reg * invW;
    float dmass = sum_hit * invW;
    float dcoh = 0.6f * msims + 0.25f * mrp + 0.15f * mrc;
    float pattern_c = 1.f - (0.6f * best + 0.2f * mrp + 0.2f * mrc);
    float contr = 0.2f * hidden_c + 0.2f * token_c + 0.6f * pattern_c;
    contr = fminf(fmaxf(contr, 0.f), 1.f);
    float sh = 0.f;
#pragma unroll
    for (int r = 0; r < RB_; r++) sh += g_shiftp[p][r];
    sh *= (1.f / H_);
    out[0 * NP_ + p] = contr;
    out[1 * NP_ + p] = sh;
    out[2 * NP_ + p] = sim;
    out[3 * NP_ + p] = hidden_c;
    out[4 * NP_ + p] = token_c;
    out[5 * NP_ + p] = pattern_c;
    out[6 * NP_ + p] = dmass;
    out[7 * NP_ + p] = dcoh;
  }
}

extern "C" void kernel_launch(void* const* d_in, const int* in_sizes, int n_in,
                              void* d_out, int out_size) {
  const float* hidden = (const float*)d_in[0];
  const float* anchor = (const float*)d_in[1];
  const int* ids = (const int*)d_in[2];
  const int* ae = (const int*)d_in[3];
  float* out = (float*)d_out;
  dim3 g(RB_, NP_);   // rb fast-varying: a pair's 8 CTAs are launch-adjacent
  k_all<<<g, 256>>>(hidden, anchor, ids, ae, out);
}